// round 10
// baseline (speedup 1.0000x reference)
#include <cuda_runtime.h>
#include <math.h>
#include <stdint.h>

#define KTAGS 64
#define DDIM  128
#define VWORDS 50000
#define NV   (VWORDS + 2)
#define BATCHN 2048
#define TLEN 256
#define BOS_TAG 63
#define EOS_TAG 62
#define TINYV 1e-45f
#define ASTR  68
#define SCL   0.015625f   // 1/64 folded scaling

typedef unsigned long long u64;

__device__ __forceinline__ u64 pack2(float lo, float hi) {
    u64 r; asm("mov.b64 %0,{%1,%2};" : "=l"(r) : "f"(lo), "f"(hi)); return r;
}
__device__ __forceinline__ u64 fma2(u64 a, u64 b, u64 c) {
    u64 d; asm("fma.rn.f32x2 %0,%1,%2,%3;" : "=l"(d) : "l"(a), "l"(b), "l"(c)); return d;
}
__device__ __forceinline__ float2 unpack2(u64 v) {
    float2 f; asm("mov.b64 {%0,%1},%2;" : "=f"(f.x), "=f"(f.y) : "l"(v)); return f;
}
// pack two fp32 -> bf16x2 (first arg = hi half)
__device__ __forceinline__ uint32_t cvt_bf16x2(float hi, float lo) {
    uint32_t r; asm("cvt.rn.bf16x2.f32 %0, %1, %2;" : "=r"(r) : "f"(hi), "f"(lo)); return r;
}
// D(16x8,f32) += A(16x16,bf16) @ B(16x8,bf16)
__device__ __forceinline__ void mma16816(float& d0, float& d1, float& d2, float& d3,
        uint32_t a0, uint32_t a1, uint32_t a2, uint32_t a3,
        uint32_t b0, uint32_t b1) {
    asm("mma.sync.aligned.m16n8k16.row.col.f32.bf16.bf16.f32 "
        "{%0,%1,%2,%3}, {%4,%5,%6,%7}, {%8,%9}, {%0,%1,%2,%3};"
        : "+f"(d0), "+f"(d1), "+f"(d2), "+f"(d3)
        : "r"(a0), "r"(a1), "r"(a2), "r"(a3), "r"(b0), "r"(b1));
}

// Scratch (static device global; no dynamic allocation)
__device__ float g_Bt[(size_t)NV * KTAGS];   // emission table, word-major [w][k]

// ---------------------------------------------------------------------------
// Kernel 1: emission table g_Bt[w][k] = exp(dot(ThetaB[k,:], E[w,:]))
// ---------------------------------------------------------------------------
__global__ __launch_bounds__(256) void emit_table_kernel(
        const float* __restrict__ ThetaB, const float* __restrict__ E) {
    __shared__ __align__(16) float sE[64 * 65];
    __shared__ __align__(16) float sTh[64 * ASTR];

    int tid = threadIdx.x;
    int wq  = tid & 15;
    int kq  = tid >> 4;
    int w0  = blockIdx.x * 64;

    u64 acc[4][2];
#pragma unroll
    for (int a = 0; a < 4; a++) { acc[a][0] = 0ull; acc[a][1] = 0ull; }

    for (int dc = 0; dc < 2; dc++) {
        for (int idx = tid; idx < 64 * 64; idx += 256) {
            int k = idx >> 6, dl = idx & 63;
            sTh[dl * ASTR + k] = ThetaB[k * DDIM + dc * 64 + dl];
        }
        for (int idx = tid; idx < 64 * 64; idx += 256) {
            int w = idx >> 6, dl = idx & 63;
            int wg = w0 + w;
            sE[w * 65 + dl] = (wg < NV) ? E[(size_t)wg * DDIM + dc * 64 + dl] : 0.0f;
        }
        __syncthreads();

#pragma unroll 8
        for (int dl = 0; dl < 64; dl++) {
            ulonglong2 th = *(const ulonglong2*)&sTh[dl * ASTR + kq * 4];
#pragma unroll
            for (int ww = 0; ww < 4; ww++) {
                float e = sE[(wq * 4 + ww) * 65 + dl];
                u64 ep = pack2(e, e);
                acc[ww][0] = fma2(ep, th.x, acc[ww][0]);
                acc[ww][1] = fma2(ep, th.y, acc[ww][1]);
            }
        }
        __syncthreads();
    }

#pragma unroll
    for (int ww = 0; ww < 4; ww++) {
        int w = w0 + wq * 4 + ww;
        if (w < NV) {
            float2 p0 = unpack2(acc[ww][0]);
            float2 p1 = unpack2(acc[ww][1]);
            float4 r;
            r.x = expf(p0.x); r.y = expf(p0.y);
            r.z = expf(p1.x); r.w = expf(p1.y);
            if (kq == 15) { r.z = TINYV; r.w = TINYV; }
            *(float4*)&g_Bt[(size_t)w * KTAGS + kq * 4] = r;
        }
    }
}

// ---------------------------------------------------------------------------
// Kernel 2: forward scan via mma.sync m16n8k16 bf16, TWO INDEPENDENT 4-warp
// groups per CTA (256 threads). Group grp (warps 4grp..4grp+3) runs its own
// 16-sentence scan with its own named barrier (bar.sync 1+grp, 128), so the
// two groups interleave on the 4 SMSPs and hide each other's exchange path.
// Within a group (R8 layout): warp wg owns output tags 16wg..16wg+15
// (nb blocks 2wg, 2wg+1), exchange = 1 STS.128 + named bar + 4 LDS.128.
// lane: g = lane>>2 (sentence row, +8 for second), q = lane&3.
// ---------------------------------------------------------------------------
__global__ __launch_bounds__(256, 1) void crf_scan_kernel(
        const float* __restrict__ WA,
        const int* __restrict__ words, float* __restrict__ out) {
    __shared__ __align__(16) float sWA[KTAGS * KTAGS];    // 16 KB
    __shared__ uint16_t sWT[TLEN][32];                     // 16 KB (vocab < 65536)
    __shared__ __align__(16) uint4 sX[2][2][4][32];        // [grp][p][kc][lane], 8 KB
    __shared__ float sZ[2][4][16];

    int tid  = threadIdx.x;
    int w    = tid >> 5;       // warp 0..7
    int grp  = w >> 2;         // group 0/1
    int wg   = w & 3;          // output-tag block within group
    int lane = tid & 31;
    int g    = lane >> 2;      // 0..7
    int q    = lane & 3;       // 0..3
    int sb   = blockIdx.x * 32;        // CTA sentence base
    int s0   = sb + grp * 16;          // group sentence base
    int srow = grp * 16 + g;           // sWT row-g index for this group

    for (int idx = tid; idx < KTAGS * KTAGS / 4; idx += 256)
        ((float4*)sWA)[idx] = ((const float4*)WA)[idx];
    for (int idx = tid; idx < 32 * TLEN; idx += 256) {
        int s = idx >> 8, tt = idx & (TLEN - 1);
        sWT[tt][s] = (uint16_t)words[(size_t)(sb + s) * TLEN + tt];
    }
    __syncthreads();

    // B fragments for own nb pair (j=0,1 -> col n = 16wg+8j+g)
    uint32_t Bf[4][2][2];
#pragma unroll
    for (int j = 0; j < 2; j++) {
        int n = 16 * wg + 8 * j + g;
        bool bos = (n == BOS_TAG);
#pragma unroll
        for (int kc = 0; kc < 4; kc++) {
            int k0 = 16 * kc + 2 * q;
            float v0 = bos ? 0.0f : expf(sWA[(k0)     * KTAGS + n]) * SCL;
            float v1 = bos ? 0.0f : expf(sWA[(k0 + 1) * KTAGS + n]) * SCL;
            float v8 = bos ? 0.0f : expf(sWA[(k0 + 8) * KTAGS + n]) * SCL;
            float v9 = bos ? 0.0f : expf(sWA[(k0 + 9) * KTAGS + n]) * SCL;
            Bf[kc][j][0] = cvt_bf16x2(v1, v0);
            Bf[kc][j][1] = cvt_bf16x2(v9, v8);
        }
    }

    // EOS column entries for this thread's 4 tags
    float eos0[2], eos1[2];
#pragma unroll
    for (int j = 0; j < 2; j++) {
        int n0 = 16 * wg + 8 * j + 2 * q;
        eos0[j] = expf(sWA[(n0)     * KTAGS + EOS_TAG]) * SCL;
        eos1[j] = expf(sWA[(n0 + 1) * KTAGS + EOS_TAG]) * SCL;
    }

    // alpha_1[s][n] = A'[BOS][n] * emis(pos 1)[n], fp32, own 16-tag slice
    float d[2][4];
    {
        int w1g  = sWT[1][srow];
        int w1g8 = sWT[1][srow + 8];
#pragma unroll
        for (int j = 0; j < 2; j++) {
            int n0 = 16 * wg + 8 * j + 2 * q;
            float rb0 = (n0     == BOS_TAG) ? 0.0f : expf(sWA[BOS_TAG * KTAGS + n0])     * SCL;
            float rb1 = (n0 + 1 == BOS_TAG) ? 0.0f : expf(sWA[BOS_TAG * KTAGS + n0 + 1]) * SCL;
            float2 eA = *(const float2*)(g_Bt + (size_t)w1g  * KTAGS + n0);
            float2 eB = *(const float2*)(g_Bt + (size_t)w1g8 * KTAGS + n0);
            d[j][0] = rb0 * eA.x; d[j][1] = rb1 * eA.y;
            d[j][2] = rb0 * eB.x; d[j][3] = rb1 * eB.y;
        }
    }

    // prefetch emissions for step t=2
    float2 eg[2], eg8[2];
    {
        int w2g  = sWT[2][srow];
        int w2g8 = sWT[2][srow + 8];
#pragma unroll
        for (int j = 0; j < 2; j++) {
            int n0 = 16 * wg + 8 * j + 2 * q;
            eg[j]  = *(const float2*)(g_Bt + (size_t)w2g  * KTAGS + n0);
            eg8[j] = *(const float2*)(g_Bt + (size_t)w2g8 * KTAGS + n0);
        }
    }

    int barid = 1 + grp;
    int p = 0;
    for (int t = 2; t <= TLEN - 2; ++t) {
        // publish own Af[wg] slice (alpha_{t-1}, bf16)
        uint4 my;
        my.x = cvt_bf16x2(d[0][1], d[0][0]);
        my.y = cvt_bf16x2(d[0][3], d[0][2]);
        my.z = cvt_bf16x2(d[1][1], d[1][0]);
        my.w = cvt_bf16x2(d[1][3], d[1][2]);
        sX[grp][p][wg][lane] = my;
        asm volatile("bar.sync %0, 128;" :: "r"(barid) : "memory");

        // gather full alpha fragment set
        uint32_t Af[4][4];
#pragma unroll
        for (int kc = 0; kc < 4; kc++) {
            uint4 v = sX[grp][p][kc][lane];
            Af[kc][0] = v.x; Af[kc][1] = v.y; Af[kc][2] = v.z; Af[kc][3] = v.w;
        }

        // D = alpha_{t-1} @ A'[:, own 16 cols]  (2 independent depth-4 chains)
#pragma unroll
        for (int j = 0; j < 2; j++) {
            d[j][0] = 0.0f; d[j][1] = 0.0f; d[j][2] = 0.0f; d[j][3] = 0.0f;
#pragma unroll
            for (int kc = 0; kc < 4; kc++)
                mma16816(d[j][0], d[j][1], d[j][2], d[j][3],
                         Af[kc][0], Af[kc][1], Af[kc][2], Af[kc][3],
                         Bf[kc][j][0], Bf[kc][j][1]);
        }

        // prefetch emissions for t+1 (after MMA issue; t=254 reads pos 255: valid, unused)
        float2 ng[2], ng8[2];
        {
            int wn  = sWT[t + 1][srow];
            int wn8 = sWT[t + 1][srow + 8];
#pragma unroll
            for (int j = 0; j < 2; j++) {
                int n0 = 16 * wg + 8 * j + 2 * q;
                ng[j]  = *(const float2*)(g_Bt + (size_t)wn  * KTAGS + n0);
                ng8[j] = *(const float2*)(g_Bt + (size_t)wn8 * KTAGS + n0);
            }
        }

        // x emissions (fp32)
#pragma unroll
        for (int j = 0; j < 2; j++) {
            d[j][0] *= eg[j].x;  d[j][1] *= eg[j].y;
            d[j][2] *= eg8[j].x; d[j][3] *= eg8[j].y;
            eg[j] = ng[j]; eg8[j] = ng8[j];
        }
        p ^= 1;
    }

    // final transition into EOS: partial over own 16 tags, then group reduce
    {
        float zg = 0.0f, zg8 = 0.0f;
#pragma unroll
        for (int j = 0; j < 2; j++) {
            zg  += d[j][0] * eos0[j] + d[j][1] * eos1[j];
            zg8 += d[j][2] * eos0[j] + d[j][3] * eos1[j];
        }
        zg  += __shfl_xor_sync(0xffffffffu, zg, 1);
        zg  += __shfl_xor_sync(0xffffffffu, zg, 2);
        zg8 += __shfl_xor_sync(0xffffffffu, zg8, 1);
        zg8 += __shfl_xor_sync(0xffffffffu, zg8, 2);
        if (q == 0) {
            sZ[grp][wg][g]     = zg;
            sZ[grp][wg][8 + g] = zg8;
        }
    }
    asm volatile("bar.sync %0, 128;" :: "r"(barid) : "memory");
    if (wg == 0 && lane < 16) {
        float z = sZ[grp][0][lane] + sZ[grp][1][lane] + sZ[grp][2][lane] + sZ[grp][3][lane];
        // + 255 * log(64) = 1530 * ln2 (fixed-scaling compensation)
        out[s0 + lane] = logf(z) + 1060.5151862567153f;
    }
}

// ---------------------------------------------------------------------------
extern "C" void kernel_launch(void* const* d_in, const int* in_sizes, int n_in,
                              void* d_out, int out_size) {
    const int*   words  = nullptr;
    const float* ThetaB = nullptr;
    const float* WA     = nullptr;
    const float* E      = nullptr;
    for (int i = 0; i < n_in; i++) {
        switch (in_sizes[i]) {
            case BATCHN * TLEN:   words  = (const int*)d_in[i];   break;
            case KTAGS * DDIM:    ThetaB = (const float*)d_in[i]; break;
            case KTAGS * KTAGS:   WA     = (const float*)d_in[i]; break;
            case NV * DDIM:       E      = (const float*)d_in[i]; break;
        }
    }
    float* out = (float*)d_out;

    emit_table_kernel<<<(NV + 63) / 64, 256>>>(ThetaB, E);
    crf_scan_kernel<<<BATCHN / 32, 256>>>(WA, words, out);
}

// round 11
// speedup vs baseline: 1.0785x; 1.0785x over previous
#include <cuda_runtime.h>
#include <math.h>
#include <stdint.h>

#define KTAGS 64
#define DDIM  128
#define VWORDS 50000
#define NV   (VWORDS + 2)
#define BATCHN 2048
#define TLEN 256
#define BOS_TAG 63
#define EOS_TAG 62
#define TINYV 1e-45f
#define ASTR  68
#define SCL   0.015625f   // 1/64 folded scaling

typedef unsigned long long u64;

template<int N> struct IC { static constexpr int value = N; };

__device__ __forceinline__ u64 pack2(float lo, float hi) {
    u64 r; asm("mov.b64 %0,{%1,%2};" : "=l"(r) : "f"(lo), "f"(hi)); return r;
}
__device__ __forceinline__ u64 fma2(u64 a, u64 b, u64 c) {
    u64 d; asm("fma.rn.f32x2 %0,%1,%2,%3;" : "=l"(d) : "l"(a), "l"(b), "l"(c)); return d;
}
__device__ __forceinline__ float2 unpack2(u64 v) {
    float2 f; asm("mov.b64 {%0,%1},%2;" : "=f"(f.x), "=f"(f.y) : "l"(v)); return f;
}
// pack two fp32 -> bf16x2 (first arg = hi half)
__device__ __forceinline__ uint32_t cvt_bf16x2(float hi, float lo) {
    uint32_t r; asm("cvt.rn.bf16x2.f32 %0, %1, %2;" : "=r"(r) : "f"(hi), "f"(lo)); return r;
}
// D(16x8,f32) += A(16x16,bf16) @ B(16x8,bf16)
__device__ __forceinline__ void mma16816(float& d0, float& d1, float& d2, float& d3,
        uint32_t a0, uint32_t a1, uint32_t a2, uint32_t a3,
        uint32_t b0, uint32_t b1) {
    asm("mma.sync.aligned.m16n8k16.row.col.f32.bf16.bf16.f32 "
        "{%0,%1,%2,%3}, {%4,%5,%6,%7}, {%8,%9}, {%0,%1,%2,%3};"
        : "+f"(d0), "+f"(d1), "+f"(d2), "+f"(d3)
        : "r"(a0), "r"(a1), "r"(a2), "r"(a3), "r"(b0), "r"(b1));
}

// Scratch (static device global; no dynamic allocation)
__device__ float g_Bt[(size_t)NV * KTAGS];   // emission table, word-major [w][k]

// ---------------------------------------------------------------------------
// Kernel 1: emission table g_Bt[w][k] = exp(dot(ThetaB[k,:], E[w,:]))
// ---------------------------------------------------------------------------
__global__ __launch_bounds__(256) void emit_table_kernel(
        const float* __restrict__ ThetaB, const float* __restrict__ E) {
    __shared__ __align__(16) float sE[64 * 65];
    __shared__ __align__(16) float sTh[64 * ASTR];

    int tid = threadIdx.x;
    int wq  = tid & 15;
    int kq  = tid >> 4;
    int w0  = blockIdx.x * 64;

    u64 acc[4][2];
#pragma unroll
    for (int a = 0; a < 4; a++) { acc[a][0] = 0ull; acc[a][1] = 0ull; }

    for (int dc = 0; dc < 2; dc++) {
        for (int idx = tid; idx < 64 * 64; idx += 256) {
            int k = idx >> 6, dl = idx & 63;
            sTh[dl * ASTR + k] = ThetaB[k * DDIM + dc * 64 + dl];
        }
        for (int idx = tid; idx < 64 * 64; idx += 256) {
            int w = idx >> 6, dl = idx & 63;
            int wg = w0 + w;
            sE[w * 65 + dl] = (wg < NV) ? E[(size_t)wg * DDIM + dc * 64 + dl] : 0.0f;
        }
        __syncthreads();

#pragma unroll 8
        for (int dl = 0; dl < 64; dl++) {
            ulonglong2 th = *(const ulonglong2*)&sTh[dl * ASTR + kq * 4];
#pragma unroll
            for (int ww = 0; ww < 4; ww++) {
                float e = sE[(wq * 4 + ww) * 65 + dl];
                u64 ep = pack2(e, e);
                acc[ww][0] = fma2(ep, th.x, acc[ww][0]);
                acc[ww][1] = fma2(ep, th.y, acc[ww][1]);
            }
        }
        __syncthreads();
    }

#pragma unroll
    for (int ww = 0; ww < 4; ww++) {
        int w = w0 + wq * 4 + ww;
        if (w < NV) {
            float2 p0 = unpack2(acc[ww][0]);
            float2 p1 = unpack2(acc[ww][1]);
            float4 r;
            r.x = __expf(p0.x); r.y = __expf(p0.y);
            r.z = __expf(p1.x); r.w = __expf(p1.y);
            if (kq == 15) { r.z = TINYV; r.w = TINYV; }
            *(float4*)&g_Bt[(size_t)w * KTAGS + kq * 4] = r;
        }
    }
}

// ---------------------------------------------------------------------------
// Kernel 2: forward scan via mma.sync m16n8k16 bf16, N-SPLIT across 4 warps
// (R8 layout) with a shortened per-step chain:
//  - depth-2 MMA chains + FADD fold (was depth-4)
//  - own-kc MMA issues BEFORE the barrier (own Af slice is in registers)
//  - 3 LDS.128 per step (own slice skipped)
//  - emission prefetch issued after the MMA block
// Warp wg owns output tags 16wg..16wg+15. Chains per j: (wg -> wg+2),
// (wg+1 -> wg+3) mod 4 — kc indices compile-time via per-wg template.
// lane: g = lane>>2 (sentence row, +8 for second), q = lane&3.
// ---------------------------------------------------------------------------
__global__ __launch_bounds__(128, 1) void crf_scan_kernel(
        const float* __restrict__ WA,
        const int* __restrict__ words, float* __restrict__ out) {
    __shared__ __align__(16) float sWA[KTAGS * KTAGS];   // 16 KB
    __shared__ int sWT[TLEN][16];                         // 16 KB
    __shared__ __align__(16) uint4 sX[2][4][32];          // 4 KB exchange
    __shared__ float sZ[4][16];

    int tid  = threadIdx.x;
    int w    = tid >> 5;      // warp 0..3 = output-tag block
    int lane = tid & 31;
    int g    = lane >> 2;     // 0..7
    int q    = lane & 3;      // 0..3
    int s0   = blockIdx.x * 16;

    for (int idx = tid; idx < KTAGS * KTAGS / 4; idx += 128)
        ((float4*)sWA)[idx] = ((const float4*)WA)[idx];
    for (int idx = tid; idx < 16 * TLEN; idx += 128) {
        int s = idx >> 8, tt = idx & (TLEN - 1);
        sWT[tt][s] = words[(size_t)(s0 + s) * TLEN + tt];
    }
    __syncthreads();

    // EOS column entries for this thread's 4 tags (no wg-template dependence)
    float eos0[2], eos1[2];
#pragma unroll
    for (int j = 0; j < 2; j++) {
        int n0 = 16 * w + 8 * j + 2 * q;
        eos0[j] = __expf(sWA[(n0)     * KTAGS + EOS_TAG]) * SCL;
        eos1[j] = __expf(sWA[(n0 + 1) * KTAGS + EOS_TAG]) * SCL;
    }

    // alpha_1[s][n] = A'[BOS][n] * emis(pos 1)[n], fp32, own 16-tag slice
    float d[2][4];
    {
        int w1g  = sWT[1][g];
        int w1g8 = sWT[1][8 + g];
#pragma unroll
        for (int j = 0; j < 2; j++) {
            int n0 = 16 * w + 8 * j + 2 * q;
            float rb0 = (n0     == BOS_TAG) ? 0.0f : __expf(sWA[BOS_TAG * KTAGS + n0])     * SCL;
            float rb1 = (n0 + 1 == BOS_TAG) ? 0.0f : __expf(sWA[BOS_TAG * KTAGS + n0 + 1]) * SCL;
            float2 eA = *(const float2*)(g_Bt + (size_t)w1g  * KTAGS + n0);
            float2 eB = *(const float2*)(g_Bt + (size_t)w1g8 * KTAGS + n0);
            d[j][0] = rb0 * eA.x; d[j][1] = rb1 * eA.y;
            d[j][2] = rb0 * eB.x; d[j][3] = rb1 * eB.y;
        }
    }

    // prefetch emissions for step t=2
    float2 eg[2], eg8[2];
    {
        int w2g  = sWT[2][g];
        int w2g8 = sWT[2][8 + g];
#pragma unroll
        for (int j = 0; j < 2; j++) {
            int n0 = 16 * w + 8 * j + 2 * q;
            eg[j]  = *(const float2*)(g_Bt + (size_t)w2g  * KTAGS + n0);
            eg8[j] = *(const float2*)(g_Bt + (size_t)w2g8 * KTAGS + n0);
        }
    }

    // The scan loop, templated on warp id so kc indices are compile-time.
    auto scan_body = [&](auto wgc) {
        constexpr int WG = decltype(wgc)::value;
        constexpr int K1 = (WG + 1) & 3;
        constexpr int K2 = (WG + 2) & 3;
        constexpr int K3 = (WG + 3) & 3;

        // B fragments for own nb pair (j=0,1 -> col n = 16*WG+8j+g)
        uint32_t Bf[4][2][2];
#pragma unroll
        for (int j = 0; j < 2; j++) {
            int n = 16 * WG + 8 * j + g;
            bool bos = (n == BOS_TAG);
#pragma unroll
            for (int kc = 0; kc < 4; kc++) {
                int k0 = 16 * kc + 2 * q;
                float v0 = bos ? 0.0f : __expf(sWA[(k0)     * KTAGS + n]) * SCL;
                float v1 = bos ? 0.0f : __expf(sWA[(k0 + 1) * KTAGS + n]) * SCL;
                float v8 = bos ? 0.0f : __expf(sWA[(k0 + 8) * KTAGS + n]) * SCL;
                float v9 = bos ? 0.0f : __expf(sWA[(k0 + 9) * KTAGS + n]) * SCL;
                Bf[kc][j][0] = cvt_bf16x2(v1, v0);
                Bf[kc][j][1] = cvt_bf16x2(v9, v8);
            }
        }

        int p = 0;
        for (int t = 2; t <= TLEN - 2; ++t) {
            // publish own Af[WG] slice (alpha_{t-1}, bf16); keep it in regs too
            uint4 my;
            my.x = cvt_bf16x2(d[0][1], d[0][0]);
            my.y = cvt_bf16x2(d[0][3], d[0][2]);
            my.z = cvt_bf16x2(d[1][1], d[1][0]);
            my.w = cvt_bf16x2(d[1][3], d[1][2]);
            sX[p][WG][lane] = my;

            // chain-A first MMA (kc = WG) has no barrier dependency: overlaps bar
            float a0[2], a1[2], a2[2], a3[2];   // chain A per j
            float b0[2], b1[2], b2[2], b3[2];   // chain B per j
#pragma unroll
            for (int j = 0; j < 2; j++) {
                a0[j] = 0.f; a1[j] = 0.f; a2[j] = 0.f; a3[j] = 0.f;
                mma16816(a0[j], a1[j], a2[j], a3[j],
                         my.x, my.y, my.z, my.w, Bf[WG][j][0], Bf[WG][j][1]);
            }

            asm volatile("bar.sync 0, 128;" ::: "memory");

            // gather the 3 other slices
            uint4 v1 = sX[p][K1][lane];
            uint4 v2 = sX[p][K2][lane];
            uint4 v3 = sX[p][K3][lane];

#pragma unroll
            for (int j = 0; j < 2; j++) {
                // chain B: K1 -> K3
                b0[j] = 0.f; b1[j] = 0.f; b2[j] = 0.f; b3[j] = 0.f;
                mma16816(b0[j], b1[j], b2[j], b3[j],
                         v1.x, v1.y, v1.z, v1.w, Bf[K1][j][0], Bf[K1][j][1]);
                // chain A second: K2
                mma16816(a0[j], a1[j], a2[j], a3[j],
                         v2.x, v2.y, v2.z, v2.w, Bf[K2][j][0], Bf[K2][j][1]);
                // chain B second: K3
                mma16816(b0[j], b1[j], b2[j], b3[j],
                         v3.x, v3.y, v3.z, v3.w, Bf[K3][j][0], Bf[K3][j][1]);
            }

            // prefetch emissions for t+1 (after MMA issue; t=254 reads pos 255: valid, unused)
            float2 ng[2], ng8[2];
            {
                int wn  = sWT[t + 1][g];
                int wn8 = sWT[t + 1][8 + g];
#pragma unroll
                for (int j = 0; j < 2; j++) {
                    int n0 = 16 * WG + 8 * j + 2 * q;
                    ng[j]  = *(const float2*)(g_Bt + (size_t)wn  * KTAGS + n0);
                    ng8[j] = *(const float2*)(g_Bt + (size_t)wn8 * KTAGS + n0);
                }
            }

            // fold chains + emission multiply (fp32)
#pragma unroll
            for (int j = 0; j < 2; j++) {
                d[j][0] = (a0[j] + b0[j]) * eg[j].x;
                d[j][1] = (a1[j] + b1[j]) * eg[j].y;
                d[j][2] = (a2[j] + b2[j]) * eg8[j].x;
                d[j][3] = (a3[j] + b3[j]) * eg8[j].y;
                eg[j] = ng[j]; eg8[j] = ng8[j];
            }
            p ^= 1;
        }
    };

    switch (w) {
        case 0: scan_body(IC<0>{}); break;
        case 1: scan_body(IC<1>{}); break;
        case 2: scan_body(IC<2>{}); break;
        default: scan_body(IC<3>{}); break;
    }

    // final transition into EOS: partial over own 16 tags, then group reduce
    {
        float zg = 0.0f, zg8 = 0.0f;
#pragma unroll
        for (int j = 0; j < 2; j++) {
            zg  += d[j][0] * eos0[j] + d[j][1] * eos1[j];
            zg8 += d[j][2] * eos0[j] + d[j][3] * eos1[j];
        }
        zg  += __shfl_xor_sync(0xffffffffu, zg, 1);
        zg  += __shfl_xor_sync(0xffffffffu, zg, 2);
        zg8 += __shfl_xor_sync(0xffffffffu, zg8, 1);
        zg8 += __shfl_xor_sync(0xffffffffu, zg8, 2);
        if (q == 0) {
            sZ[w][g]     = zg;
            sZ[w][8 + g] = zg8;
        }
    }
    __syncthreads();
    if (tid < 16) {
        float z = sZ[0][tid] + sZ[1][tid] + sZ[2][tid] + sZ[3][tid];
        // + 255 * log(64) = 1530 * ln2 (fixed-scaling compensation)
        out[s0 + tid] = logf(z) + 1060.5151862567153f;
    }
}

// ---------------------------------------------------------------------------
extern "C" void kernel_launch(void* const* d_in, const int* in_sizes, int n_in,
                              void* d_out, int out_size) {
    const int*   words  = nullptr;
    const float* ThetaB = nullptr;
    const float* WA     = nullptr;
    const float* E      = nullptr;
    for (int i = 0; i < n_in; i++) {
        switch (in_sizes[i]) {
            case BATCHN * TLEN:   words  = (const int*)d_in[i];   break;
            case KTAGS * DDIM:    ThetaB = (const float*)d_in[i]; break;
            case KTAGS * KTAGS:   WA     = (const float*)d_in[i]; break;
            case NV * DDIM:       E      = (const float*)d_in[i]; break;
        }
    }
    float* out = (float*)d_out;

    emit_table_kernel<<<(NV + 63) / 64, 256>>>(ThetaB, E);
    crf_scan_kernel<<<BATCHN / 16, 128>>>(WA, words, out);
}

// round 12
// speedup vs baseline: 1.3300x; 1.2332x over previous
#include <cuda_runtime.h>
#include <math.h>
#include <stdint.h>

#define KTAGS 64
#define DDIM  128
#define VWORDS 50000
#define NV   (VWORDS + 2)
#define BATCHN 2048
#define TLEN 256
#define BOS_TAG 63
#define EOS_TAG 62
#define TINYV 1e-45f
#define SCL   0.015625f   // 1/64 folded scaling

typedef unsigned long long u64;

// pack two fp32 -> bf16x2 (first arg = hi half)
__device__ __forceinline__ uint32_t cvt_bf16x2(float hi, float lo) {
    uint32_t r; asm("cvt.rn.bf16x2.f32 %0, %1, %2;" : "=r"(r) : "f"(hi), "f"(lo)); return r;
}
// D(16x8,f32) += A(16x16,bf16) @ B(16x8,bf16)
__device__ __forceinline__ void mma16816(float& d0, float& d1, float& d2, float& d3,
        uint32_t a0, uint32_t a1, uint32_t a2, uint32_t a3,
        uint32_t b0, uint32_t b1) {
    asm("mma.sync.aligned.m16n8k16.row.col.f32.bf16.bf16.f32 "
        "{%0,%1,%2,%3}, {%4,%5,%6,%7}, {%8,%9}, {%0,%1,%2,%3};"
        : "+f"(d0), "+f"(d1), "+f"(d2), "+f"(d3)
        : "r"(a0), "r"(a1), "r"(a2), "r"(a3), "r"(b0), "r"(b1));
}

// Scratch (static device global; no dynamic allocation)
__device__ float g_Bt[(size_t)NV * KTAGS];   // emission table, word-major [w][k]

// ---------------------------------------------------------------------------
// Kernel 1: emission table via bf16 tensor cores.
// g_Bt[w][k] = exp(dot(ThetaB[k,:], E[w,:])); tags 62/63 forced to TINY.
// CTA = 256 threads = 8 warps; warp handles 16 words (one m16 tile), k=128
// as 8 kc-chunks. B = ThetaB^T fragments staged in smem once per CTA.
// ---------------------------------------------------------------------------
__global__ __launch_bounds__(256) void emit_table_kernel(
        const float* __restrict__ ThetaB, const float* __restrict__ E) {
    __shared__ __align__(16) uint2 sBf[8][8][32];   // [kc][nb][lane], 16 KB

    int tid  = threadIdx.x;
    int w    = tid >> 5;
    int lane = tid & 31;
    int g    = lane >> 2;
    int q    = lane & 3;

    // stage B fragments: n = 8nb+gg, k0 = 16kc+2qq
    for (int idx = tid; idx < 2048; idx += 256) {
        int kc = idx >> 8, nb = (idx >> 5) & 7, ln = idx & 31;
        int gg = ln >> 2, qq = ln & 3;
        int n  = 8 * nb + gg;
        int k0 = 16 * kc + 2 * qq;
        uint2 b;
        b.x = cvt_bf16x2(ThetaB[n * DDIM + k0 + 1], ThetaB[n * DDIM + k0]);
        b.y = cvt_bf16x2(ThetaB[n * DDIM + k0 + 9], ThetaB[n * DDIM + k0 + 8]);
        sBf[kc][nb][ln] = b;
    }
    __syncthreads();

    int w0 = (blockIdx.x * 8 + w) * 16;        // word-tile base
    int r0 = w0 + g;     if (r0 >= NV) r0 = NV - 1;
    int r1 = w0 + g + 8; if (r1 >= NV) r1 = NV - 1;
    const float* e0p = E + (size_t)r0 * DDIM;
    const float* e1p = E + (size_t)r1 * DDIM;

    // A fragments: rows g / g+8 of the tile
    uint32_t Afr[8][4];
#pragma unroll
    for (int kc = 0; kc < 8; kc++) {
        int k0 = 16 * kc + 2 * q;
        float2 x0 = *(const float2*)(e0p + k0);
        float2 x1 = *(const float2*)(e1p + k0);
        float2 y0 = *(const float2*)(e0p + k0 + 8);
        float2 y1 = *(const float2*)(e1p + k0 + 8);
        Afr[kc][0] = cvt_bf16x2(x0.y, x0.x);
        Afr[kc][1] = cvt_bf16x2(x1.y, x1.x);
        Afr[kc][2] = cvt_bf16x2(y0.y, y0.x);
        Afr[kc][3] = cvt_bf16x2(y1.y, y1.x);
    }

    float acc[8][4];
#pragma unroll
    for (int nb = 0; nb < 8; nb++) {
        acc[nb][0] = 0.f; acc[nb][1] = 0.f; acc[nb][2] = 0.f; acc[nb][3] = 0.f;
#pragma unroll
        for (int kc = 0; kc < 8; kc++) {
            uint2 b = sBf[kc][nb][lane];
            mma16816(acc[nb][0], acc[nb][1], acc[nb][2], acc[nb][3],
                     Afr[kc][0], Afr[kc][1], Afr[kc][2], Afr[kc][3], b.x, b.y);
        }
    }

    // exp + TINY override for tags 62/63, write two float2 per nb
#pragma unroll
    for (int nb = 0; nb < 8; nb++) {
        int n0 = 8 * nb + 2 * q;
        float v0 = __expf(acc[nb][0]);
        float v1 = __expf(acc[nb][1]);
        float v2 = __expf(acc[nb][2]);
        float v3 = __expf(acc[nb][3]);
        if (nb == 7 && q == 3) { v0 = TINYV; v1 = TINYV; v2 = TINYV; v3 = TINYV; }
        if (w0 + g < NV)
            *(float2*)&g_Bt[(size_t)(w0 + g) * KTAGS + n0]     = make_float2(v0, v1);
        if (w0 + g + 8 < NV)
            *(float2*)&g_Bt[(size_t)(w0 + g + 8) * KTAGS + n0] = make_float2(v2, v3);
    }
}

// ---------------------------------------------------------------------------
// Kernel 2: forward scan via mma.sync m16n8k16 bf16, N-SPLIT across 4 warps
// (exact R8 layout; single change: emission prefetch moved AFTER the MMAs).
// Warp w owns output tags 16w..16w+15 (nb blocks 2w, 2w+1).
// Exchange: 1 STS.128 + __syncthreads + 4 LDS.128, no shuffles.
// lane: g = lane>>2 (sentence row, +8 for second), q = lane&3.
// ---------------------------------------------------------------------------
__global__ __launch_bounds__(128, 1) void crf_scan_kernel(
        const float* __restrict__ WA,
        const int* __restrict__ words, float* __restrict__ out) {
    __shared__ __align__(16) float sWA[KTAGS * KTAGS];   // 16 KB
    __shared__ int sWT[TLEN][16];                         // 16 KB
    __shared__ __align__(16) uint4 sX[2][4][32];          // 4 KB exchange
    __shared__ float sZ[4][16];

    int tid  = threadIdx.x;
    int w    = tid >> 5;      // warp 0..3 = output-tag block
    int lane = tid & 31;
    int g    = lane >> 2;     // 0..7
    int q    = lane & 3;      // 0..3
    int s0   = blockIdx.x * 16;

    for (int idx = tid; idx < KTAGS * KTAGS / 4; idx += 128)
        ((float4*)sWA)[idx] = ((const float4*)WA)[idx];
    for (int idx = tid; idx < 16 * TLEN; idx += 128) {
        int s = idx >> 8, tt = idx & (TLEN - 1);
        sWT[tt][s] = words[(size_t)(s0 + s) * TLEN + tt];
    }
    __syncthreads();

    // B fragments for own nb pair (j=0,1 -> nb = 2w+j, col n = 16w+8j+g)
    uint32_t Bf[4][2][2];
#pragma unroll
    for (int j = 0; j < 2; j++) {
        int n = 16 * w + 8 * j + g;
        bool bos = (n == BOS_TAG);
#pragma unroll
        for (int kc = 0; kc < 4; kc++) {
            int k0 = 16 * kc + 2 * q;
            float v0 = bos ? 0.0f : __expf(sWA[(k0)     * KTAGS + n]) * SCL;
            float v1 = bos ? 0.0f : __expf(sWA[(k0 + 1) * KTAGS + n]) * SCL;
            float v8 = bos ? 0.0f : __expf(sWA[(k0 + 8) * KTAGS + n]) * SCL;
            float v9 = bos ? 0.0f : __expf(sWA[(k0 + 9) * KTAGS + n]) * SCL;
            Bf[kc][j][0] = cvt_bf16x2(v1, v0);
            Bf[kc][j][1] = cvt_bf16x2(v9, v8);
        }
    }

    // EOS column entries for this thread's 4 tags
    float eos0[2], eos1[2];
#pragma unroll
    for (int j = 0; j < 2; j++) {
        int n0 = 16 * w + 8 * j + 2 * q;
        eos0[j] = __expf(sWA[(n0)     * KTAGS + EOS_TAG]) * SCL;
        eos1[j] = __expf(sWA[(n0 + 1) * KTAGS + EOS_TAG]) * SCL;
    }

    // alpha_1[s][n] = A'[BOS][n] * emis(pos 1)[n], fp32, own 16-tag slice
    float d[2][4];
    {
        int w1g  = sWT[1][g];
        int w1g8 = sWT[1][8 + g];
#pragma unroll
        for (int j = 0; j < 2; j++) {
            int n0 = 16 * w + 8 * j + 2 * q;
            float rb0 = (n0     == BOS_TAG) ? 0.0f : __expf(sWA[BOS_TAG * KTAGS + n0])     * SCL;
            float rb1 = (n0 + 1 == BOS_TAG) ? 0.0f : __expf(sWA[BOS_TAG * KTAGS + n0 + 1]) * SCL;
            float2 eA = *(const float2*)(g_Bt + (size_t)w1g  * KTAGS + n0);
            float2 eB = *(const float2*)(g_Bt + (size_t)w1g8 * KTAGS + n0);
            d[j][0] = rb0 * eA.x; d[j][1] = rb1 * eA.y;
            d[j][2] = rb0 * eB.x; d[j][3] = rb1 * eB.y;
        }
    }

    // prefetch emissions for step t=2
    float2 eg[2], eg8[2];
    {
        int w2g  = sWT[2][g];
        int w2g8 = sWT[2][8 + g];
#pragma unroll
        for (int j = 0; j < 2; j++) {
            int n0 = 16 * w + 8 * j + 2 * q;
            eg[j]  = *(const float2*)(g_Bt + (size_t)w2g  * KTAGS + n0);
            eg8[j] = *(const float2*)(g_Bt + (size_t)w2g8 * KTAGS + n0);
        }
    }

    int p = 0;
    for (int t = 2; t <= TLEN - 2; ++t) {
        // publish own Af[w] slice (alpha_{t-1}, bf16)
        uint4 my;
        my.x = cvt_bf16x2(d[0][1], d[0][0]);
        my.y = cvt_bf16x2(d[0][3], d[0][2]);
        my.z = cvt_bf16x2(d[1][1], d[1][0]);
        my.w = cvt_bf16x2(d[1][3], d[1][2]);
        sX[p][w][lane] = my;
        __syncthreads();

        // gather full alpha fragment set (critical path: straight to MMAs)
        uint32_t Af[4][4];
#pragma unroll
        for (int kc = 0; kc < 4; kc++) {
            uint4 v = sX[p][kc][lane];
            Af[kc][0] = v.x; Af[kc][1] = v.y; Af[kc][2] = v.z; Af[kc][3] = v.w;
        }

        // D = alpha_{t-1} @ A'[:, own 16 cols]
#pragma unroll
        for (int j = 0; j < 2; j++) {
            d[j][0] = 0.0f; d[j][1] = 0.0f; d[j][2] = 0.0f; d[j][3] = 0.0f;
#pragma unroll
            for (int kc = 0; kc < 4; kc++)
                mma16816(d[j][0], d[j][1], d[j][2], d[j][3],
                         Af[kc][0], Af[kc][1], Af[kc][2], Af[kc][3],
                         Bf[kc][j][0], Bf[kc][j][1]);
        }

        // prefetch emissions for t+1 (after MMA issue; t=254 reads pos 255: valid, unused)
        float2 ng[2], ng8[2];
        {
            int wn  = sWT[t + 1][g];
            int wn8 = sWT[t + 1][8 + g];
#pragma unroll
            for (int j = 0; j < 2; j++) {
                int n0 = 16 * w + 8 * j + 2 * q;
                ng[j]  = *(const float2*)(g_Bt + (size_t)wn  * KTAGS + n0);
                ng8[j] = *(const float2*)(g_Bt + (size_t)wn8 * KTAGS + n0);
            }
        }

        // x emissions (fp32)
#pragma unroll
        for (int j = 0; j < 2; j++) {
            d[j][0] *= eg[j].x;  d[j][1] *= eg[j].y;
            d[j][2] *= eg8[j].x; d[j][3] *= eg8[j].y;
            eg[j] = ng[j]; eg8[j] = ng8[j];
        }
        p ^= 1;
    }

    // final transition into EOS: partial over own 16 tags, then group reduce
    {
        float zg = 0.0f, zg8 = 0.0f;
#pragma unroll
        for (int j = 0; j < 2; j++) {
            zg  += d[j][0] * eos0[j] + d[j][1] * eos1[j];
            zg8 += d[j][2] * eos0[j] + d[j][3] * eos1[j];
        }
        zg  += __shfl_xor_sync(0xffffffffu, zg, 1);
        zg  += __shfl_xor_sync(0xffffffffu, zg, 2);
        zg8 += __shfl_xor_sync(0xffffffffu, zg8, 1);
        zg8 += __shfl_xor_sync(0xffffffffu, zg8, 2);
        if (q == 0) {
            sZ[w][g]     = zg;
            sZ[w][8 + g] = zg8;
        }
    }
    __syncthreads();
    if (tid < 16) {
        float z = sZ[0][tid] + sZ[1][tid] + sZ[2][tid] + sZ[3][tid];
        // + 255 * log(64) = 1530 * ln2 (fixed-scaling compensation)
        out[s0 + tid] = logf(z) + 1060.5151862567153f;
    }
}

// ---------------------------------------------------------------------------
extern "C" void kernel_launch(void* const* d_in, const int* in_sizes, int n_in,
                              void* d_out, int out_size) {
    const int*   words  = nullptr;
    const float* ThetaB = nullptr;
    const float* WA     = nullptr;
    const float* E      = nullptr;
    for (int i = 0; i < n_in; i++) {
        switch (in_sizes[i]) {
            case BATCHN * TLEN:   words  = (const int*)d_in[i];   break;
            case KTAGS * DDIM:    ThetaB = (const float*)d_in[i]; break;
            case KTAGS * KTAGS:   WA     = (const float*)d_in[i]; break;
            case NV * DDIM:       E      = (const float*)d_in[i]; break;
        }
    }
    float* out = (float*)d_out;

    emit_table_kernel<<<(NV + 127) / 128, 256>>>(ThetaB, E);
    crf_scan_kernel<<<BATCHN / 16, 128>>>(WA, words, out);
}

// round 13
// speedup vs baseline: 1.3310x; 1.0007x over previous
#include <cuda_runtime.h>
#include <math.h>
#include <stdint.h>

#define KTAGS 64
#define DDIM  128
#define VWORDS 50000
#define NV   (VWORDS + 2)
#define BATCHN 2048
#define TLEN 256
#define BOS_TAG 63
#define EOS_TAG 62
#define TINYV 1e-45f
#define SCL   0.015625f   // 1/64 folded scaling

typedef unsigned long long u64;

// pack two fp32 -> bf16x2 (first arg = hi half)
__device__ __forceinline__ uint32_t cvt_bf16x2(float hi, float lo) {
    uint32_t r; asm("cvt.rn.bf16x2.f32 %0, %1, %2;" : "=r"(r) : "f"(hi), "f"(lo)); return r;
}
// D(16x8,f32) += A(16x16,bf16) @ B(16x8,bf16)
__device__ __forceinline__ void mma16816(float& d0, float& d1, float& d2, float& d3,
        uint32_t a0, uint32_t a1, uint32_t a2, uint32_t a3,
        uint32_t b0, uint32_t b1) {
    asm("mma.sync.aligned.m16n8k16.row.col.f32.bf16.bf16.f32 "
        "{%0,%1,%2,%3}, {%4,%5,%6,%7}, {%8,%9}, {%0,%1,%2,%3};"
        : "+f"(d0), "+f"(d1), "+f"(d2), "+f"(d3)
        : "r"(a0), "r"(a1), "r"(a2), "r"(a3), "r"(b0), "r"(b1));
}

// Scratch (static device global; no dynamic allocation)
__device__ float g_Bt[(size_t)NV * KTAGS];   // emission table, word-major [w][k]

// ---------------------------------------------------------------------------
// Kernel 1: emission table via bf16 tensor cores.
// g_Bt[w][k] = exp(dot(ThetaB[k,:], E[w,:])); tags 62/63 forced to TINY.
// ---------------------------------------------------------------------------
__global__ __launch_bounds__(256) void emit_table_kernel(
        const float* __restrict__ ThetaB, const float* __restrict__ E) {
    __shared__ __align__(16) uint2 sBf[8][8][32];   // [kc][nb][lane], 16 KB

    int tid  = threadIdx.x;
    int w    = tid >> 5;
    int lane = tid & 31;
    int g    = lane >> 2;
    int q    = lane & 3;

    // stage B fragments: n = 8nb+gg, k0 = 16kc+2qq
    for (int idx = tid; idx < 2048; idx += 256) {
        int kc = idx >> 8, nb = (idx >> 5) & 7, ln = idx & 31;
        int gg = ln >> 2, qq = ln & 3;
        int n  = 8 * nb + gg;
        int k0 = 16 * kc + 2 * qq;
        uint2 b;
        b.x = cvt_bf16x2(ThetaB[n * DDIM + k0 + 1], ThetaB[n * DDIM + k0]);
        b.y = cvt_bf16x2(ThetaB[n * DDIM + k0 + 9], ThetaB[n * DDIM + k0 + 8]);
        sBf[kc][nb][ln] = b;
    }
    __syncthreads();

    int w0 = (blockIdx.x * 8 + w) * 16;        // word-tile base
    int r0 = w0 + g;     if (r0 >= NV) r0 = NV - 1;
    int r1 = w0 + g + 8; if (r1 >= NV) r1 = NV - 1;
    const float* e0p = E + (size_t)r0 * DDIM;
    const float* e1p = E + (size_t)r1 * DDIM;

    // A fragments: rows g / g+8 of the tile
    uint32_t Afr[8][4];
#pragma unroll
    for (int kc = 0; kc < 8; kc++) {
        int k0 = 16 * kc + 2 * q;
        float2 x0 = *(const float2*)(e0p + k0);
        float2 x1 = *(const float2*)(e1p + k0);
        float2 y0 = *(const float2*)(e0p + k0 + 8);
        float2 y1 = *(const float2*)(e1p + k0 + 8);
        Afr[kc][0] = cvt_bf16x2(x0.y, x0.x);
        Afr[kc][1] = cvt_bf16x2(x1.y, x1.x);
        Afr[kc][2] = cvt_bf16x2(y0.y, y0.x);
        Afr[kc][3] = cvt_bf16x2(y1.y, y1.x);
    }

    float acc[8][4];
#pragma unroll
    for (int nb = 0; nb < 8; nb++) {
        acc[nb][0] = 0.f; acc[nb][1] = 0.f; acc[nb][2] = 0.f; acc[nb][3] = 0.f;
#pragma unroll
        for (int kc = 0; kc < 8; kc++) {
            uint2 b = sBf[kc][nb][lane];
            mma16816(acc[nb][0], acc[nb][1], acc[nb][2], acc[nb][3],
                     Afr[kc][0], Afr[kc][1], Afr[kc][2], Afr[kc][3], b.x, b.y);
        }
    }

    // exp + TINY override for tags 62/63, write two float2 per nb
#pragma unroll
    for (int nb = 0; nb < 8; nb++) {
        int n0 = 8 * nb + 2 * q;
        float v0 = __expf(acc[nb][0]);
        float v1 = __expf(acc[nb][1]);
        float v2 = __expf(acc[nb][2]);
        float v3 = __expf(acc[nb][3]);
        if (nb == 7 && q == 3) { v0 = TINYV; v1 = TINYV; v2 = TINYV; v3 = TINYV; }
        if (w0 + g < NV)
            *(float2*)&g_Bt[(size_t)(w0 + g) * KTAGS + n0]     = make_float2(v0, v1);
        if (w0 + g + 8 < NV)
            *(float2*)&g_Bt[(size_t)(w0 + g + 8) * KTAGS + n0] = make_float2(v2, v3);
    }
}

// ---------------------------------------------------------------------------
// Kernel 2: forward scan via mma.sync m16n8k16 bf16, N-SPLIT across 4 warps.
// R12 layout; SINGLE change this round: per-j accumulation split into two
// independent depth-2 MMA chains (kc0->kc1, kc2->kc3) folded by one FADD,
// cutting the dependent-HMMA depth from 4 to 2 on the serial path.
// Warp w owns output tags 16w..16w+15 (nb blocks 2w, 2w+1).
// Exchange: 1 STS.128 + __syncthreads + 4 LDS.128, no shuffles.
// lane: g = lane>>2 (sentence row, +8 for second), q = lane&3.
// ---------------------------------------------------------------------------
__global__ __launch_bounds__(128, 1) void crf_scan_kernel(
        const float* __restrict__ WA,
        const int* __restrict__ words, float* __restrict__ out) {
    __shared__ __align__(16) float sWA[KTAGS * KTAGS];   // 16 KB
    __shared__ int sWT[TLEN][16];                         // 16 KB
    __shared__ __align__(16) uint4 sX[2][4][32];          // 4 KB exchange
    __shared__ float sZ[4][16];

    int tid  = threadIdx.x;
    int w    = tid >> 5;      // warp 0..3 = output-tag block
    int lane = tid & 31;
    int g    = lane >> 2;     // 0..7
    int q    = lane & 3;      // 0..3
    int s0   = blockIdx.x * 16;

    for (int idx = tid; idx < KTAGS * KTAGS / 4; idx += 128)
        ((float4*)sWA)[idx] = ((const float4*)WA)[idx];
    for (int idx = tid; idx < 16 * TLEN; idx += 128) {
        int s = idx >> 8, tt = idx & (TLEN - 1);
        sWT[tt][s] = words[(size_t)(s0 + s) * TLEN + tt];
    }
    __syncthreads();

    // B fragments for own nb pair (j=0,1 -> nb = 2w+j, col n = 16w+8j+g)
    uint32_t Bf[4][2][2];
#pragma unroll
    for (int j = 0; j < 2; j++) {
        int n = 16 * w + 8 * j + g;
        bool bos = (n == BOS_TAG);
#pragma unroll
        for (int kc = 0; kc < 4; kc++) {
            int k0 = 16 * kc + 2 * q;
            float v0 = bos ? 0.0f : __expf(sWA[(k0)     * KTAGS + n]) * SCL;
            float v1 = bos ? 0.0f : __expf(sWA[(k0 + 1) * KTAGS + n]) * SCL;
            float v8 = bos ? 0.0f : __expf(sWA[(k0 + 8) * KTAGS + n]) * SCL;
            float v9 = bos ? 0.0f : __expf(sWA[(k0 + 9) * KTAGS + n]) * SCL;
            Bf[kc][j][0] = cvt_bf16x2(v1, v0);
            Bf[kc][j][1] = cvt_bf16x2(v9, v8);
        }
    }

    // EOS column entries for this thread's 4 tags
    float eos0[2], eos1[2];
#pragma unroll
    for (int j = 0; j < 2; j++) {
        int n0 = 16 * w + 8 * j + 2 * q;
        eos0[j] = __expf(sWA[(n0)     * KTAGS + EOS_TAG]) * SCL;
        eos1[j] = __expf(sWA[(n0 + 1) * KTAGS + EOS_TAG]) * SCL;
    }

    // alpha_1[s][n] = A'[BOS][n] * emis(pos 1)[n], fp32, own 16-tag slice
    float d[2][4];
    {
        int w1g  = sWT[1][g];
        int w1g8 = sWT[1][8 + g];
#pragma unroll
        for (int j = 0; j < 2; j++) {
            int n0 = 16 * w + 8 * j + 2 * q;
            float rb0 = (n0     == BOS_TAG) ? 0.0f : __expf(sWA[BOS_TAG * KTAGS + n0])     * SCL;
            float rb1 = (n0 + 1 == BOS_TAG) ? 0.0f : __expf(sWA[BOS_TAG * KTAGS + n0 + 1]) * SCL;
            float2 eA = *(const float2*)(g_Bt + (size_t)w1g  * KTAGS + n0);
            float2 eB = *(const float2*)(g_Bt + (size_t)w1g8 * KTAGS + n0);
            d[j][0] = rb0 * eA.x; d[j][1] = rb1 * eA.y;
            d[j][2] = rb0 * eB.x; d[j][3] = rb1 * eB.y;
        }
    }

    // prefetch emissions for step t=2
    float2 eg[2], eg8[2];
    {
        int w2g  = sWT[2][g];
        int w2g8 = sWT[2][8 + g];
#pragma unroll
        for (int j = 0; j < 2; j++) {
            int n0 = 16 * w + 8 * j + 2 * q;
            eg[j]  = *(const float2*)(g_Bt + (size_t)w2g  * KTAGS + n0);
            eg8[j] = *(const float2*)(g_Bt + (size_t)w2g8 * KTAGS + n0);
        }
    }

    int p = 0;
    for (int t = 2; t <= TLEN - 2; ++t) {
        // publish own Af[w] slice (alpha_{t-1}, bf16)
        uint4 my;
        my.x = cvt_bf16x2(d[0][1], d[0][0]);
        my.y = cvt_bf16x2(d[0][3], d[0][2]);
        my.z = cvt_bf16x2(d[1][1], d[1][0]);
        my.w = cvt_bf16x2(d[1][3], d[1][2]);
        sX[p][w][lane] = my;
        __syncthreads();

        // gather full alpha fragment set (critical path: straight to MMAs)
        uint32_t Af[4][4];
#pragma unroll
        for (int kc = 0; kc < 4; kc++) {
            uint4 v = sX[p][kc][lane];
            Af[kc][0] = v.x; Af[kc][1] = v.y; Af[kc][2] = v.z; Af[kc][3] = v.w;
        }

        // D = alpha_{t-1} @ A'[:, own 16 cols]
        // per j: two independent depth-2 chains (kc0->kc1, kc2->kc3), FADD fold
        float a[2][4], b[2][4];
#pragma unroll
        for (int j = 0; j < 2; j++) {
            a[j][0] = 0.f; a[j][1] = 0.f; a[j][2] = 0.f; a[j][3] = 0.f;
            b[j][0] = 0.f; b[j][1] = 0.f; b[j][2] = 0.f; b[j][3] = 0.f;
            mma16816(a[j][0], a[j][1], a[j][2], a[j][3],
                     Af[0][0], Af[0][1], Af[0][2], Af[0][3], Bf[0][j][0], Bf[0][j][1]);
            mma16816(b[j][0], b[j][1], b[j][2], b[j][3],
                     Af[2][0], Af[2][1], Af[2][2], Af[2][3], Bf[2][j][0], Bf[2][j][1]);
            mma16816(a[j][0], a[j][1], a[j][2], a[j][3],
                     Af[1][0], Af[1][1], Af[1][2], Af[1][3], Bf[1][j][0], Bf[1][j][1]);
            mma16816(b[j][0], b[j][1], b[j][2], b[j][3],
                     Af[3][0], Af[3][1], Af[3][2], Af[3][3], Bf[3][j][0], Bf[3][j][1]);
        }

        // prefetch emissions for t+1 (after MMA issue; t=254 reads pos 255: valid, unused)
        float2 ng[2], ng8[2];
        {
            int wn  = sWT[t + 1][g];
            int wn8 = sWT[t + 1][8 + g];
#pragma unroll
            for (int j = 0; j < 2; j++) {
                int n0 = 16 * w + 8 * j + 2 * q;
                ng[j]  = *(const float2*)(g_Bt + (size_t)wn  * KTAGS + n0);
                ng8[j] = *(const float2*)(g_Bt + (size_t)wn8 * KTAGS + n0);
            }
        }

        // fold chains + emission multiply (fp32)
#pragma unroll
        for (int j = 0; j < 2; j++) {
            d[j][0] = (a[j][0] + b[j][0]) * eg[j].x;
            d[j][1] = (a[j][1] + b[j][1]) * eg[j].y;
            d[j][2] = (a[j][2] + b[j][2]) * eg8[j].x;
            d[j][3] = (a[j][3] + b[j][3]) * eg8[j].y;
            eg[j] = ng[j]; eg8[j] = ng8[j];
        }
        p ^= 1;
    }

    // final transition into EOS: partial over own 16 tags, then group reduce
    {
        float zg = 0.0f, zg8 = 0.0f;
#pragma unroll
        for (int j = 0; j < 2; j++) {
            zg  += d[j][0] * eos0[j] + d[j][1] * eos1[j];
            zg8 += d[j][2] * eos0[j] + d[j][3] * eos1[j];
        }
        zg  += __shfl_xor_sync(0xffffffffu, zg, 1);
        zg  += __shfl_xor_sync(0xffffffffu, zg, 2);
        zg8 += __shfl_xor_sync(0xffffffffu, zg8, 1);
        zg8 += __shfl_xor_sync(0xffffffffu, zg8, 2);
        if (q == 0) {
            sZ[w][g]     = zg;
            sZ[w][8 + g] = zg8;
        }
    }
    __syncthreads();
    if (tid < 16) {
        float z = sZ[0][tid] + sZ[1][tid] + sZ[2][tid] + sZ[3][tid];
        // + 255 * log(64) = 1530 * ln2 (fixed-scaling compensation)
        out[s0 + tid] = logf(z) + 1060.5151862567153f;
    }
}

// ---------------------------------------------------------------------------
extern "C" void kernel_launch(void* const* d_in, const int* in_sizes, int n_in,
                              void* d_out, int out_size) {
    const int*   words  = nullptr;
    const float* ThetaB = nullptr;
    const float* WA     = nullptr;
    const float* E      = nullptr;
    for (int i = 0; i < n_in; i++) {
        switch (in_sizes[i]) {
            case BATCHN * TLEN:   words  = (const int*)d_in[i];   break;
            case KTAGS * DDIM:    ThetaB = (const float*)d_in[i]; break;
            case KTAGS * KTAGS:   WA     = (const float*)d_in[i]; break;
            case NV * DDIM:       E      = (const float*)d_in[i]; break;
        }
    }
    float* out = (float*)d_out;

    emit_table_kernel<<<(NV + 127) / 128, 256>>>(ThetaB, E);
    crf_scan_kernel<<<BATCHN / 16, 128>>>(WA, words, out);
}

// round 14
// speedup vs baseline: 1.4530x; 1.0916x over previous
#include <cuda_runtime.h>
#include <cuda_fp16.h>
#include <math.h>
#include <stdint.h>

#define KTAGS 64
#define DDIM  128
#define VWORDS 50000
#define NV   (VWORDS + 2)
#define BATCHN 2048
#define TLEN 256
#define BOS_TAG 63
#define EOS_TAG 62
#define TINYV 1e-45f
#define SCL   0.015625f   // 1/64 folded scaling

typedef unsigned long long u64;

// pack two fp32 -> bf16x2 (first arg = hi half)
__device__ __forceinline__ uint32_t cvt_bf16x2(float hi, float lo) {
    uint32_t r; asm("cvt.rn.bf16x2.f32 %0, %1, %2;" : "=r"(r) : "f"(hi), "f"(lo)); return r;
}
// pack two fp32 -> f16x2 (first arg = hi half)
__device__ __forceinline__ uint32_t cvt_f16x2(float hi, float lo) {
    uint32_t r; asm("cvt.rn.f16x2.f32 %0, %1, %2;" : "=r"(r) : "f"(hi), "f"(lo)); return r;
}
__device__ __forceinline__ uint32_t hadd2(uint32_t a, uint32_t b) {
    uint32_t d; asm("add.rn.f16x2 %0,%1,%2;" : "=r"(d) : "r"(a), "r"(b)); return d;
}
__device__ __forceinline__ uint32_t hmul2(uint32_t a, uint32_t b) {
    uint32_t d; asm("mul.rn.f16x2 %0,%1,%2;" : "=r"(d) : "r"(a), "r"(b)); return d;
}
__device__ __forceinline__ float2 h2f2(uint32_t v) {
    __half2 h = *reinterpret_cast<__half2*>(&v);
    return __half22float2(h);
}
// bf16 MMA, f32 accum (emit table)
__device__ __forceinline__ void mma16816(float& d0, float& d1, float& d2, float& d3,
        uint32_t a0, uint32_t a1, uint32_t a2, uint32_t a3,
        uint32_t b0, uint32_t b1) {
    asm("mma.sync.aligned.m16n8k16.row.col.f32.bf16.bf16.f32 "
        "{%0,%1,%2,%3}, {%4,%5,%6,%7}, {%8,%9}, {%0,%1,%2,%3};"
        : "+f"(d0), "+f"(d1), "+f"(d2), "+f"(d3)
        : "r"(a0), "r"(a1), "r"(a2), "r"(a3), "r"(b0), "r"(b1));
}
// f16 MMA, f16 accum (scan): D {c0=row g cols 2q/2q+1, c1=row g+8}
__device__ __forceinline__ void mma16816h(uint32_t& c0, uint32_t& c1,
        uint32_t a0, uint32_t a1, uint32_t a2, uint32_t a3,
        uint32_t b0, uint32_t b1) {
    asm("mma.sync.aligned.m16n8k16.row.col.f16.f16.f16.f16 "
        "{%0,%1}, {%2,%3,%4,%5}, {%6,%7}, {%0,%1};"
        : "+r"(c0), "+r"(c1)
        : "r"(a0), "r"(a1), "r"(a2), "r"(a3), "r"(b0), "r"(b1));
}

// Scratch (static device global; no dynamic allocation)
// emission table, word-major, f16x2 packed: [w][32] u32, word (2c,2c+1)
__device__ uint32_t g_Bt16[(size_t)NV * 32];

// ---------------------------------------------------------------------------
// Kernel 1: emission table via bf16 tensor cores, f16x2 output.
// g_Bt16[w][c] = f16x2(exp(ThetaB[2c,:]·E[w,:]), exp(ThetaB[2c+1,:]·E[w,:]))
// tags 62/63 forced to TINY (flushes to 0 in f16; contribution ~1e-45).
// ---------------------------------------------------------------------------
__global__ __launch_bounds__(256) void emit_table_kernel(
        const float* __restrict__ ThetaB, const float* __restrict__ E) {
    __shared__ __align__(16) uint2 sBf[8][8][32];   // [kc][nb][lane], 16 KB

    int tid  = threadIdx.x;
    int w    = tid >> 5;
    int lane = tid & 31;
    int g    = lane >> 2;
    int q    = lane & 3;

    for (int idx = tid; idx < 2048; idx += 256) {
        int kc = idx >> 8, nb = (idx >> 5) & 7, ln = idx & 31;
        int gg = ln >> 2, qq = ln & 3;
        int n  = 8 * nb + gg;
        int k0 = 16 * kc + 2 * qq;
        uint2 b;
        b.x = cvt_bf16x2(ThetaB[n * DDIM + k0 + 1], ThetaB[n * DDIM + k0]);
        b.y = cvt_bf16x2(ThetaB[n * DDIM + k0 + 9], ThetaB[n * DDIM + k0 + 8]);
        sBf[kc][nb][ln] = b;
    }
    __syncthreads();

    int w0 = (blockIdx.x * 8 + w) * 16;
    int r0 = w0 + g;     if (r0 >= NV) r0 = NV - 1;
    int r1 = w0 + g + 8; if (r1 >= NV) r1 = NV - 1;
    const float* e0p = E + (size_t)r0 * DDIM;
    const float* e1p = E + (size_t)r1 * DDIM;

    uint32_t Afr[8][4];
#pragma unroll
    for (int kc = 0; kc < 8; kc++) {
        int k0 = 16 * kc + 2 * q;
        float2 x0 = *(const float2*)(e0p + k0);
        float2 x1 = *(const float2*)(e1p + k0);
        float2 y0 = *(const float2*)(e0p + k0 + 8);
        float2 y1 = *(const float2*)(e1p + k0 + 8);
        Afr[kc][0] = cvt_bf16x2(x0.y, x0.x);
        Afr[kc][1] = cvt_bf16x2(x1.y, x1.x);
        Afr[kc][2] = cvt_bf16x2(y0.y, y0.x);
        Afr[kc][3] = cvt_bf16x2(y1.y, y1.x);
    }

    float acc[8][4];
#pragma unroll
    for (int nb = 0; nb < 8; nb++) {
        acc[nb][0] = 0.f; acc[nb][1] = 0.f; acc[nb][2] = 0.f; acc[nb][3] = 0.f;
#pragma unroll
        for (int kc = 0; kc < 8; kc++) {
            uint2 b = sBf[kc][nb][lane];
            mma16816(acc[nb][0], acc[nb][1], acc[nb][2], acc[nb][3],
                     Afr[kc][0], Afr[kc][1], Afr[kc][2], Afr[kc][3], b.x, b.y);
        }
    }

#pragma unroll
    for (int nb = 0; nb < 8; nb++) {
        int cidx = 4 * nb + q;     // column-pair index (tags 2c, 2c+1)
        float v0 = __expf(acc[nb][0]);
        float v1 = __expf(acc[nb][1]);
        float v2 = __expf(acc[nb][2]);
        float v3 = __expf(acc[nb][3]);
        if (nb == 7 && q == 3) { v0 = TINYV; v1 = TINYV; v2 = TINYV; v3 = TINYV; }
        if (w0 + g < NV)
            g_Bt16[(size_t)(w0 + g) * 32 + cidx]     = cvt_f16x2(v1, v0);
        if (w0 + g + 8 < NV)
            g_Bt16[(size_t)(w0 + g + 8) * 32 + cidx] = cvt_f16x2(v3, v2);
    }
}

// ---------------------------------------------------------------------------
// Kernel 2: forward scan via mma.sync m16n8k16, FULL f16 datapath:
//  - f16 inputs AND f16 accumulate -> D is 2 packed f16x2 regs
//  - published slice = d regs directly (NO CVT on the critical path)
//  - 4 independent depth-1 MMAs per j + HADD2 tree + HMUL2 emission (f16x2)
//  - emission table f16x2: one 4-byte load per (j, row)
// Warp w owns output tags 16w..16w+15 (nb blocks 2w, 2w+1).
// Exchange: 1 STS.128 + __syncthreads + 4 LDS.128, no shuffles.
// lane: g = lane>>2 (sentence row, +8 for second), q = lane&3.
// ---------------------------------------------------------------------------
__global__ __launch_bounds__(128, 1) void crf_scan_kernel(
        const float* __restrict__ WA,
        const int* __restrict__ words, float* __restrict__ out) {
    __shared__ __align__(16) float sWA[KTAGS * KTAGS];   // 16 KB
    __shared__ int sWT[TLEN][16];                         // 16 KB
    __shared__ __align__(16) uint4 sX[2][4][32];          // 4 KB exchange
    __shared__ float sZ[4][16];

    int tid  = threadIdx.x;
    int w    = tid >> 5;      // warp 0..3 = output-tag block
    int lane = tid & 31;
    int g    = lane >> 2;     // 0..7
    int q    = lane & 3;      // 0..3
    int s0   = blockIdx.x * 16;

    for (int idx = tid; idx < KTAGS * KTAGS / 4; idx += 128)
        ((float4*)sWA)[idx] = ((const float4*)WA)[idx];
    for (int idx = tid; idx < 16 * TLEN; idx += 128) {
        int s = idx >> 8, tt = idx & (TLEN - 1);
        sWT[tt][s] = words[(size_t)(s0 + s) * TLEN + tt];
    }
    __syncthreads();

    // B fragments (f16) for own nb pair (j=0,1 -> col n = 16w+8j+g)
    uint32_t Bf[4][2][2];
#pragma unroll
    for (int j = 0; j < 2; j++) {
        int n = 16 * w + 8 * j + g;
        bool bos = (n == BOS_TAG);
#pragma unroll
        for (int kc = 0; kc < 4; kc++) {
            int k0 = 16 * kc + 2 * q;
            float v0 = bos ? 0.0f : __expf(sWA[(k0)     * KTAGS + n]) * SCL;
            float v1 = bos ? 0.0f : __expf(sWA[(k0 + 1) * KTAGS + n]) * SCL;
            float v8 = bos ? 0.0f : __expf(sWA[(k0 + 8) * KTAGS + n]) * SCL;
            float v9 = bos ? 0.0f : __expf(sWA[(k0 + 9) * KTAGS + n]) * SCL;
            Bf[kc][j][0] = cvt_f16x2(v1, v0);
            Bf[kc][j][1] = cvt_f16x2(v9, v8);
        }
    }

    // EOS column entries for this thread's 4 tags (fp32)
    float eos0[2], eos1[2];
#pragma unroll
    for (int j = 0; j < 2; j++) {
        int n0 = 16 * w + 8 * j + 2 * q;
        eos0[j] = __expf(sWA[(n0)     * KTAGS + EOS_TAG]) * SCL;
        eos1[j] = __expf(sWA[(n0 + 1) * KTAGS + EOS_TAG]) * SCL;
    }

    int cidx[2];                       // f16x2 column-pair index per j
    cidx[0] = 8 * w + q;
    cidx[1] = 8 * w + 4 + q;

    // alpha_1[s][n] = A'[BOS][n] * emis(pos 1)[n]; d[j] = {row g, row g+8} f16x2
    uint32_t d[2][2];
    {
        int w1g  = sWT[1][g];
        int w1g8 = sWT[1][8 + g];
#pragma unroll
        for (int j = 0; j < 2; j++) {
            int n0 = 16 * w + 8 * j + 2 * q;
            float rb0 = (n0     == BOS_TAG) ? 0.0f : __expf(sWA[BOS_TAG * KTAGS + n0])     * SCL;
            float rb1 = (n0 + 1 == BOS_TAG) ? 0.0f : __expf(sWA[BOS_TAG * KTAGS + n0 + 1]) * SCL;
            float2 eA = h2f2(g_Bt16[(size_t)w1g  * 32 + cidx[j]]);
            float2 eB = h2f2(g_Bt16[(size_t)w1g8 * 32 + cidx[j]]);
            d[j][0] = cvt_f16x2(rb1 * eA.y, rb0 * eA.x);
            d[j][1] = cvt_f16x2(rb1 * eB.y, rb0 * eB.x);
        }
    }

    // prefetch emissions for step t=2 (f16x2, one u32 per (j,row))
    uint32_t eg[2][2];
    {
        int w2g  = sWT[2][g];
        int w2g8 = sWT[2][8 + g];
#pragma unroll
        for (int j = 0; j < 2; j++) {
            eg[j][0] = g_Bt16[(size_t)w2g  * 32 + cidx[j]];
            eg[j][1] = g_Bt16[(size_t)w2g8 * 32 + cidx[j]];
        }
    }

    int p = 0;
    for (int t = 2; t <= TLEN - 2; ++t) {
        // publish own Af[w] slice — d regs ARE the fragment, no conversion
        uint4 my;
        my.x = d[0][0]; my.y = d[0][1]; my.z = d[1][0]; my.w = d[1][1];
        sX[p][w][lane] = my;
        __syncthreads();

        // gather full alpha fragment set
        uint32_t Af[4][4];
#pragma unroll
        for (int kc = 0; kc < 4; kc++) {
            uint4 v = sX[p][kc][lane];
            Af[kc][0] = v.x; Af[kc][1] = v.y; Af[kc][2] = v.z; Af[kc][3] = v.w;
        }

        // 4 independent depth-1 MMAs per j (f16 accum)
        uint32_t c[2][4][2];
#pragma unroll
        for (int j = 0; j < 2; j++) {
#pragma unroll
            for (int kc = 0; kc < 4; kc++) {
                c[j][kc][0] = 0u; c[j][kc][1] = 0u;
                mma16816h(c[j][kc][0], c[j][kc][1],
                          Af[kc][0], Af[kc][1], Af[kc][2], Af[kc][3],
                          Bf[kc][j][0], Bf[kc][j][1]);
            }
        }

        // prefetch emissions for t+1 (t=254 reads pos 255: valid, unused)
        uint32_t ng[2][2];
        {
            int wn  = sWT[t + 1][g];
            int wn8 = sWT[t + 1][8 + g];
#pragma unroll
            for (int j = 0; j < 2; j++) {
                ng[j][0] = g_Bt16[(size_t)wn  * 32 + cidx[j]];
                ng[j][1] = g_Bt16[(size_t)wn8 * 32 + cidx[j]];
            }
        }

        // HADD2 tree fold + HMUL2 emission
#pragma unroll
        for (int j = 0; j < 2; j++) {
#pragma unroll
            for (int r = 0; r < 2; r++) {
                uint32_t s01 = hadd2(c[j][0][r], c[j][1][r]);
                uint32_t s23 = hadd2(c[j][2][r], c[j][3][r]);
                d[j][r] = hmul2(hadd2(s01, s23), eg[j][r]);
                eg[j][r] = ng[j][r];
            }
        }
        p ^= 1;
    }

    // final transition into EOS (fp32): partial over own 16 tags, then reduce
    {
        float zg = 0.0f, zg8 = 0.0f;
#pragma unroll
        for (int j = 0; j < 2; j++) {
            float2 f0 = h2f2(d[j][0]);
            float2 f1 = h2f2(d[j][1]);
            zg  += f0.x * eos0[j] + f0.y * eos1[j];
            zg8 += f1.x * eos0[j] + f1.y * eos1[j];
        }
        zg  += __shfl_xor_sync(0xffffffffu, zg, 1);
        zg  += __shfl_xor_sync(0xffffffffu, zg, 2);
        zg8 += __shfl_xor_sync(0xffffffffu, zg8, 1);
        zg8 += __shfl_xor_sync(0xffffffffu, zg8, 2);
        if (q == 0) {
            sZ[w][g]     = zg;
            sZ[w][8 + g] = zg8;
        }
    }
    __syncthreads();
    if (tid < 16) {
        float z = sZ[0][tid] + sZ[1][tid] + sZ[2][tid] + sZ[3][tid];
        // + 255 * log(64) = 1530 * ln2 (fixed-scaling compensation)
        out[s0 + tid] = logf(z) + 1060.5151862567153f;
    }
}

// ---------------------------------------------------------------------------
extern "C" void kernel_launch(void* const* d_in, const int* in_sizes, int n_in,
                              void* d_out, int out_size) {
    const int*   words  = nullptr;
    const float* ThetaB = nullptr;
    const float* WA     = nullptr;
    const float* E      = nullptr;
    for (int i = 0; i < n_in; i++) {
        switch (in_sizes[i]) {
            case BATCHN * TLEN:   words  = (const int*)d_in[i];   break;
            case KTAGS * DDIM:    ThetaB = (const float*)d_in[i]; break;
            case KTAGS * KTAGS:   WA     = (const float*)d_in[i]; break;
            case NV * DDIM:       E      = (const float*)d_in[i]; break;
        }
    }
    float* out = (float*)d_out;

    emit_table_kernel<<<(NV + 127) / 128, 256>>>(ThetaB, E);
    crf_scan_kernel<<<BATCHN / 16, 128>>>(WA, words, out);
}